// round 3
// baseline (speedup 1.0000x reference)
#include <cuda_runtime.h>
#include <cuda_bf16.h>
#include <cstdint>

// ---------------- problem constants ----------------
#define N_TOKENS 16384
#define D_MODEL  4096
#define N_EXP    64
#define N_OUT    128            // gate(64) || noise(64) logits
#define KC       32             // K chunk
#define ASTR     40             // smem row stride in bf16 (conflict-free for frag loads)
#define STG_ELEM (128 * ASTR)   // bf16 elements per stage per array = 5120
#define STG_BYTE (STG_ELEM * 2) // 10240
#define NC       (D_MODEL / KC) // 128 chunks
#define TAU      3e-4f          // near-tie refinement threshold (~10 sigma of GEMM error)

// ---------------- device scratch (no allocs allowed) ----------------
__device__ float          g_logits[(size_t)N_TOKENS * N_OUT];   // [t][0:64]=clean, [64:128]=raw_noise
__device__ __nv_bfloat16  g_bhi[(size_t)N_OUT * D_MODEL];       // W^T hi  [n][k]
__device__ __nv_bfloat16  g_blo[(size_t)N_OUT * D_MODEL];       // W^T lo  [n][k]
__device__ float          g_imp[N_EXP];
__device__ float          g_load[N_EXP];
__device__ int            g_nflag;
__device__ int            g_flag[N_TOKENS];

// ---------------- cp.async helpers ----------------
#define CP_ASYNC16(dst, src)                                                        \
    asm volatile("cp.async.cg.shared.global [%0], [%1], 16;\n" ::"r"(dst), "l"(src))
#define CP_COMMIT()  asm volatile("cp.async.commit_group;\n" ::)
#define CP_WAIT1()   asm volatile("cp.async.wait_group 1;\n" ::)

// ---------------- prep: transpose + bf16 split, zero accumulators ----------------
__global__ void __launch_bounds__(256) prep_kernel(const float* __restrict__ wg,
                                                   const float* __restrict__ wn) {
    int gid = blockIdx.x * blockDim.x + threadIdx.x;
    if (gid < N_EXP) { g_imp[gid] = 0.f; g_load[gid] = 0.f; }
    if (gid == N_EXP) g_nflag = 0;
    int stride = gridDim.x * blockDim.x;
    const int total = N_OUT * D_MODEL;
    for (int i = gid; i < total; i += stride) {
        int n = i >> 12;          // /4096
        int k = i & 4095;
        float w = (n < N_EXP) ? wg[k * N_EXP + n] : wn[k * N_EXP + (n - N_EXP)];
        __nv_bfloat16 h = __float2bfloat16(w);
        g_bhi[i] = h;
        g_blo[i] = __float2bfloat16(w - __bfloat162float(h));
    }
}

// ---------------- GEMM: logits = inp @ [w_gate | w_noise], fp32 via bf16 split ----------------
#define MMA_BF16(d, a, b0v, b1v)                                                    \
    asm volatile("mma.sync.aligned.m16n8k16.row.col.f32.bf16.bf16.f32 "             \
                 "{%0,%1,%2,%3}, {%4,%5,%6,%7}, {%8,%9}, {%0,%1,%2,%3};"            \
                 : "+f"(d[0]), "+f"(d[1]), "+f"(d[2]), "+f"(d[3])                   \
                 : "r"(a[0]), "r"(a[1]), "r"(a[2]), "r"(a[3]), "r"(b0v), "r"(b1v))

__global__ void __launch_bounds__(256) gemm_kernel(const float* __restrict__ inp) {
    extern __shared__ __nv_bfloat16 sm[];
    __nv_bfloat16* sAhi = sm;                    // [2][STG_ELEM]
    __nv_bfloat16* sAlo = sm + 2 * STG_ELEM;
    __nv_bfloat16* sBhi = sm + 4 * STG_ELEM;
    __nv_bfloat16* sBlo = sm + 6 * STG_ELEM;

    const int tid  = threadIdx.x;
    const int wid  = tid >> 5, lane = tid & 31;
    const int wm   = wid & 3;          // warp row tile (32 rows)
    const int wn   = wid >> 2;         // warp col tile (64 cols)
    const int g    = lane >> 2, tg = lane & 3;
    const int row0 = blockIdx.x * 128;

    float acc[2][8][4];
#pragma unroll
    for (int a = 0; a < 2; a++)
#pragma unroll
        for (int b = 0; b < 8; b++)
#pragma unroll
            for (int c = 0; c < 4; c++) acc[a][b][c] = 0.f;

    const int lr = tid >> 1;           // load row (A) / n (B)
    const int lc = (tid & 1) * 16;     // col base within chunk

    const float* aSrc = inp + (size_t)(row0 + lr) * D_MODEL + lc;
    const __nv_bfloat16* bhSrc = g_bhi + (size_t)lr * D_MODEL + lc;
    const __nv_bfloat16* blSrc = g_blo + (size_t)lr * D_MODEL + lc;
    const uint32_t sBhiAddr = (uint32_t)__cvta_generic_to_shared(sBhi) + (lr * ASTR + lc) * 2;
    const uint32_t sBloAddr = (uint32_t)__cvta_generic_to_shared(sBlo) + (lr * ASTR + lc) * 2;

    float4 aR[4];

    // cp.async B chunk c into stage s
#define CPB(c, s)                                                          \
    do {                                                                   \
        CP_ASYNC16(sBhiAddr + (s)*STG_BYTE,      bhSrc + (c)*KC);          \
        CP_ASYNC16(sBhiAddr + (s)*STG_BYTE + 16, bhSrc + (c)*KC + 8);      \
        CP_ASYNC16(sBloAddr + (s)*STG_BYTE,      blSrc + (c)*KC);          \
        CP_ASYNC16(sBloAddr + (s)*STG_BYTE + 16, blSrc + (c)*KC + 8);      \
    } while (0)

#define LDA(c)                                                             \
    do {                                                                   \
        _Pragma("unroll")                                                  \
        for (int u = 0; u < 4; u++)                                        \
            aR[u] = *reinterpret_cast<const float4*>(aSrc + (c)*KC + u*4); \
    } while (0)

#define CONVSTORE(s)                                                                   \
    do {                                                                               \
        int off0 = (s)*STG_ELEM + lr * ASTR + lc;                                      \
        _Pragma("unroll")                                                              \
        for (int u = 0; u < 4; u++) {                                                  \
            float4 v = aR[u];                                                          \
            __nv_bfloat16 h0 = __float2bfloat16(v.x);                                  \
            __nv_bfloat16 h1 = __float2bfloat16(v.y);                                  \
            __nv_bfloat16 h2 = __float2bfloat16(v.z);                                  \
            __nv_bfloat16 h3 = __float2bfloat16(v.w);                                  \
            __nv_bfloat16 l0 = __float2bfloat16(v.x - __bfloat162float(h0));           \
            __nv_bfloat16 l1 = __float2bfloat16(v.y - __bfloat162float(h1));           \
            __nv_bfloat16 l2 = __float2bfloat16(v.z - __bfloat162float(h2));           \
            __nv_bfloat16 l3 = __float2bfloat16(v.w - __bfloat162float(h3));           \
            int off = off0 + u * 4;                                                    \
            *reinterpret_cast<__nv_bfloat162*>(&sAhi[off])     = __halves2bfloat162(h0, h1); \
            *reinterpret_cast<__nv_bfloat162*>(&sAhi[off + 2]) = __halves2bfloat162(h2, h3); \
            *reinterpret_cast<__nv_bfloat162*>(&sAlo[off])     = __halves2bfloat162(l0, l1); \
            *reinterpret_cast<__nv_bfloat162*>(&sAlo[off + 2]) = __halves2bfloat162(l2, l3); \
        }                                                                              \
    } while (0)

    // ---- prologue ----
    LDA(0);
    CPB(0, 0); CP_COMMIT();        // group for chunk 0
    CONVSTORE(0);
    CPB(1, 1); CP_COMMIT();        // group for chunk 1
    LDA(1);
    CP_WAIT1();                    // chunk 0 B landed
    __syncthreads();

    for (int i = 0; i < NC; i++) {
        const int p = i & 1;
        const int ab = p * STG_ELEM;

        // ---- MMA on stage p ----
#pragma unroll
        for (int ks = 0; ks < KC; ks += 16) {
            uint32_t ah[2][4], al[2][4];
#pragma unroll
            for (int mi = 0; mi < 2; mi++) {
                int r = wm * 32 + mi * 16 + g;
                int c = ks + tg * 2;
                ah[mi][0] = *reinterpret_cast<const uint32_t*>(&sAhi[ab + r * ASTR + c]);
                ah[mi][1] = *reinterpret_cast<const uint32_t*>(&sAhi[ab + (r + 8) * ASTR + c]);
                ah[mi][2] = *reinterpret_cast<const uint32_t*>(&sAhi[ab + r * ASTR + c + 8]);
                ah[mi][3] = *reinterpret_cast<const uint32_t*>(&sAhi[ab + (r + 8) * ASTR + c + 8]);
                al[mi][0] = *reinterpret_cast<const uint32_t*>(&sAlo[ab + r * ASTR + c]);
                al[mi][1] = *reinterpret_cast<const uint32_t*>(&sAlo[ab + (r + 8) * ASTR + c]);
                al[mi][2] = *reinterpret_cast<const uint32_t*>(&sAlo[ab + r * ASTR + c + 8]);
                al[mi][3] = *reinterpret_cast<const uint32_t*>(&sAlo[ab + (r + 8) * ASTR + c + 8]);
            }
#pragma unroll
            for (int ni = 0; ni < 8; ni++) {
                int nn = wn * 64 + ni * 8 + g;
                uint32_t bh0 = *reinterpret_cast<const uint32_t*>(&sBhi[ab + nn * ASTR + ks + tg * 2]);
                uint32_t bh1 = *reinterpret_cast<const uint32_t*>(&sBhi[ab + nn * ASTR + ks + tg * 2 + 8]);
                uint32_t bl0 = *reinterpret_cast<const uint32_t*>(&sBlo[ab + nn * ASTR + ks + tg * 2]);
                uint32_t bl1 = *reinterpret_cast<const uint32_t*>(&sBlo[ab + nn * ASTR + ks + tg * 2 + 8]);
#pragma unroll
                for (int mi = 0; mi < 2; mi++) {
                    MMA_BF16(acc[mi][ni], ah[mi], bh0, bh1);   // hi*hi
                    MMA_BF16(acc[mi][ni], al[mi], bh0, bh1);   // lo*hi
                    MMA_BF16(acc[mi][ni], ah[mi], bl0, bl1);   // hi*lo
                }
            }
        }
        __syncthreads();                         // all warps done reading stage p

        if (i + 1 < NC) {
            CONVSTORE(p ^ 1);                    // A for chunk i+1 (held in aR)
            if (i + 2 < NC) { CPB(i + 2, p); }   // B for chunk i+2 into freed stage p
            CP_COMMIT();                         // always commit (empty group ok)
            if (i + 2 < NC) { LDA(i + 2); }
            CP_WAIT1();                          // chunk i+1's B group complete
            __syncthreads();
        }
    }

    // epilogue -> g_logits [t][128]
#pragma unroll
    for (int mi = 0; mi < 2; mi++)
#pragma unroll
        for (int ni = 0; ni < 8; ni++) {
            int r = row0 + wm * 32 + mi * 16 + g;
            int c = wn * 64 + ni * 8 + tg * 2;
            *reinterpret_cast<float2*>(&g_logits[(size_t)r * N_OUT + c]) =
                make_float2(acc[mi][ni][0], acc[mi][ni][1]);
            *reinterpret_cast<float2*>(&g_logits[(size_t)(r + 8) * N_OUT + c]) =
                make_float2(acc[mi][ni][2], acc[mi][ni][3]);
        }
#undef CPB
#undef LDA
#undef CONVSTORE
}

// ---------------- gating helpers ----------------
__device__ __forceinline__ void warp_argmax(float& v, int& i) {
#pragma unroll
    for (int o = 16; o; o >>= 1) {
        float ov = __shfl_xor_sync(0xffffffffu, v, o);
        int   oi = __shfl_xor_sync(0xffffffffu, i, o);
        if (ov > v || (ov == v && oi < i)) { v = ov; i = oi; }
    }
}

// ---------------- gating pass 1: flag near-ties, process the rest ----------------
__global__ void __launch_bounds__(256) gate_kernel(const float* __restrict__ noise,
                                                   float* __restrict__ out) {
    __shared__ float s_imp[N_EXP];
    __shared__ float s_load[N_EXP];
    const int tid = threadIdx.x;
    if (tid < N_EXP) { s_imp[tid] = 0.f; s_load[tid] = 0.f; }
    __syncthreads();

    const int wid = tid >> 5, lane = tid & 31;
    const int e0 = 2 * lane, e1 = 2 * lane + 1;
    const int warpg = blockIdx.x * 8 + wid;   // 1024 warps total, 16 tokens each

    float li0 = 0.f, li1 = 0.f, ll0 = 0.f, ll1 = 0.f;

    for (int it = 0; it < 16; it++) {
        int t = warpg * 16 + it;
        const float* rowp = g_logits + (size_t)t * N_OUT;
        float2 cl = *reinterpret_cast<const float2*>(rowp + e0);
        float2 rn = *reinterpret_cast<const float2*>(rowp + 64 + e0);
        float2 nz = *reinterpret_cast<const float2*>(noise + (size_t)t * N_EXP + e0);

        float sp0 = fmaxf(rn.x, 0.f) + log1pf(expf(-fabsf(rn.x))) + 0.01f;
        float sp1 = fmaxf(rn.y, 0.f) + log1pf(expf(-fabsf(rn.y))) + 0.01f;
        float ny0 = cl.x + nz.x * sp0;
        float ny1 = cl.y + nz.y * sp1;

        // ---- top-3 with stable (lower index) tie-break ----
        float bv; int bi;
        if (ny0 >= ny1) { bv = ny0; bi = e0; } else { bv = ny1; bi = e1; }
        warp_argmax(bv, bi);
        float m1 = bv; int j1 = bi;

        float w0 = (e0 == j1) ? -3.4e38f : ny0;
        float w1 = (e1 == j1) ? -3.4e38f : ny1;
        if (w0 >= w1) { bv = w0; bi = e0; } else { bv = w1; bi = e1; }
        warp_argmax(bv, bi);
        float m2 = bv; int j2 = bi;

        w0 = (e0 == j2) ? -3.4e38f : w0;
        w1 = (e1 == j2) ? -3.4e38f : w1;
        if (w0 >= w1) { bv = w0; bi = e0; } else { bv = w1; bi = e1; }
        warp_argmax(bv, bi);
        float m3 = bv;

        // ---- near-tie? defer the whole token to the exact refine pass ----
        bool flagged = (m1 - m2 < TAU) || (m2 - m3 < TAU);
        if (flagged) {
            if (lane == 0) {
                int s = atomicAdd(&g_nflag, 1);
                g_flag[s] = t;
            }
            continue;
        }

        // ---- top-2 softmax ----
        float ee = expf(m2 - m1);
        float inv = 1.f / (1.f + ee);
        float gg0 = inv, gg1 = ee * inv;

        if (lane == 0) {
            out[2 * t]               = (float)j1;
            out[2 * t + 1]           = (float)j2;
            out[2 * N_TOKENS + 2 * t]     = gg0;
            out[2 * N_TOKENS + 2 * t + 1] = gg1;
        }

        // importance
        if (e0 == j1) li0 += gg0; else if (e0 == j2) li0 += gg1;
        if (e1 == j1) li1 += gg0; else if (e1 == j2) li1 += gg1;

        // load: threshold_if_in = 3rd largest (m3), else 2nd (m2)
        float thr0 = (ny0 > m3) ? m3 : m2;
        float thr1 = (ny1 > m3) ? m3 : m2;
        ll0 += normcdff((cl.x - thr0) / sp0);
        ll1 += normcdff((cl.y - thr1) / sp1);
    }

    atomicAdd(&s_imp[e0], li0);  atomicAdd(&s_imp[e1], li1);
    atomicAdd(&s_load[e0], ll0); atomicAdd(&s_load[e1], ll1);
    __syncthreads();
    if (tid < N_EXP) {
        atomicAdd(&g_imp[tid],  s_imp[tid]);
        atomicAdd(&g_load[tid], s_load[tid]);
    }
}

// ---------------- refine: fp64-exact recompute of flagged tokens ----------------
__global__ void __launch_bounds__(256) refine_kernel(const float* __restrict__ inp,
                                                     const float* __restrict__ wg,
                                                     const float* __restrict__ wn,
                                                     const float* __restrict__ noise,
                                                     float* __restrict__ out) {
    __shared__ float  sA[D_MODEL];          // token's input row
    __shared__ double sD[2][N_OUT];         // per-half fp64 partials
    __shared__ float  sL[N_OUT];            // final logits

    const int tid  = threadIdx.x;
    const int n    = tid & 127;             // output column (0..127)
    const int half = tid >> 7;              // k-range half
    const float* wptr = (n < N_EXP) ? wg : wn;
    const int nn = n & (N_EXP - 1);

    const int nf = g_nflag;

    for (int i = blockIdx.x; i < nf; i += gridDim.x) {
        const int t = g_flag[i];
        __syncthreads();
        for (int k = tid; k < D_MODEL; k += 256) sA[k] = inp[(size_t)t * D_MODEL + k];
        __syncthreads();

        // ---- fp64 dot, 8 independent chains for DFMA-latency hiding ----
        double s0 = 0, s1 = 0, s2 = 0, s3 = 0, s4 = 0, s5 = 0, s6 = 0, s7 = 0;
        const int k0 = half * (D_MODEL / 2);
        for (int k = k0; k < k0 + D_MODEL / 2; k += 8) {
            s0 = fma((double)sA[k + 0], (double)__ldg(&wptr[(size_t)(k + 0) * N_EXP + nn]), s0);
            s1 = fma((double)sA[k + 1], (double)__ldg(&wptr[(size_t)(k + 1) * N_EXP + nn]), s1);
            s2 = fma((double)sA[k + 2], (double)__ldg(&wptr[(size_t)(k + 2) * N_EXP + nn]), s2);
            s3 = fma((double)sA[k + 3], (double)__ldg(&wptr[(size_t)(k + 3) * N_EXP + nn]), s3);
            s4 = fma((double)sA[k + 4], (double)__ldg(&wptr[(size_t)(k + 4) * N_EXP + nn]), s4);
            s5 = fma((double)sA[k + 5], (double)__ldg(&wptr[(size_t)(k + 5) * N_EXP + nn]), s5);
            s6 = fma((double)sA[k + 6], (double)__ldg(&wptr[(size_t)(k + 6) * N_EXP + nn]), s6);
            s7 = fma((double)sA[k + 7], (double)__ldg(&wptr[(size_t)(k + 7) * N_EXP + nn]), s7);
        }
        sD[half][n] = ((s0 + s1) + (s2 + s3)) + ((s4 + s5) + (s6 + s7));
        __syncthreads();
        if (tid < N_OUT) sL[tid] = (float)(sD[0][tid] + sD[1][tid]);
        __syncthreads();

        // ---- gating on exact logits (warp 0 only) ----
        if (tid < 32) {
            const int lane = tid;
            const int e0 = 2 * lane, e1 = 2 * lane + 1;
            float cl0 = sL[e0], cl1 = sL[e1];
            float rn0 = sL[64 + e0], rn1 = sL[64 + e1];
            float nz0 = noise[(size_t)t * N_EXP + e0];
            float nz1 = noise[(size_t)t * N_EXP + e1];

            float sp0 = fmaxf(rn0, 0.f) + log1pf(expf(-fabsf(rn0))) + 0.01f;
            float sp1 = fmaxf(rn1, 0.f) + log1pf(expf(-fabsf(rn1))) + 0.01f;
            float ny0 = cl0 + nz0 * sp0;
            float ny1 = cl1 + nz1 * sp1;

            float bv; int bi;
            if (ny0 >= ny1) { bv = ny0; bi = e0; } else { bv = ny1; bi = e1; }
            warp_argmax(bv, bi);
            float m1 = bv; int j1 = bi;

            float w0 = (e0 == j1) ? -3.4e38f : ny0;
            float w1 = (e1 == j1) ? -3.4e38f : ny1;
            if (w0 >= w1) { bv = w0; bi = e0; } else { bv = w1; bi = e1; }
            warp_argmax(bv, bi);
            float m2 = bv; int j2 = bi;

            w0 = (e0 == j2) ? -3.4e38f : w0;
            w1 = (e1 == j2) ? -3.4e38f : w1;
            if (w0 >= w1) { bv = w0; bi = e0; } else { bv = w1; bi = e1; }
            warp_argmax(bv, bi);
            float m3 = bv;

            float ee  = expf(m2 - m1);
            float inv = 1.f / (1.f + ee);
            float gg0 = inv, gg1 = ee * inv;

            if (lane == 0) {
                out[2 * t]                    = (float)j1;
                out[2 * t + 1]                = (float)j2;
                out[2 * N_TOKENS + 2 * t]     = gg0;
                out[2 * N_TOKENS + 2 * t + 1] = gg1;
            }

            float li0 = 0.f, li1 = 0.f;
            if (e0 == j1) li0 = gg0; else if (e0 == j2) li0 = gg1;
            if (e1 == j1) li1 = gg0; else if (e1 == j2) li1 = gg1;

            float thr0 = (ny0 > m3) ? m3 : m2;
            float thr1 = (ny1 > m3) ? m3 : m2;
            float ll0 = normcdff((cl0 - thr0) / sp0);
            float ll1 = normcdff((cl1 - thr1) / sp1);

            if (li0 != 0.f) atomicAdd(&g_imp[e0], li0);
            if (li1 != 0.f) atomicAdd(&g_imp[e1], li1);
            atomicAdd(&g_load[e0], ll0);
            atomicAdd(&g_load[e1], ll1);
        }
    }
}

// ---------------- loss: cv^2(importance) + cv^2(load) ----------------
__global__ void loss_kernel(float* __restrict__ out) {
    if (threadIdx.x == 0 && blockIdx.x == 0) {
        float loss = 0.f;
        for (int pass = 0; pass < 2; pass++) {
            const float* a = pass ? g_load : g_imp;
            float s = 0.f;
            for (int e = 0; e < N_EXP; e++) s += a[e];
            float mean = s * (1.f / N_EXP);
            float v = 0.f;
            for (int e = 0; e < N_EXP; e++) { float d = a[e] - mean; v += d * d; }
            v *= (1.f / (N_EXP - 1));
            loss += v / (mean * mean + 1e-10f);
        }
        out[2 * N_TOKENS * 2] = loss;   // index 65536
    }
}

// ---------------- launch ----------------
extern "C" void kernel_launch(void* const* d_in, const int* in_sizes, int n_in,
                              void* d_out, int out_size) {
    const float* inp   = (const float*)d_in[0];
    const float* wg    = (const float*)d_in[1];
    const float* wn    = (const float*)d_in[2];
    const float* noise = (const float*)d_in[3];
    float* out = (float*)d_out;

    static bool attr_done = false;
    if (!attr_done) {
        cudaFuncSetAttribute(gemm_kernel, cudaFuncAttributeMaxDynamicSharedMemorySize,
                             8 * STG_BYTE);
        attr_done = true;
    }

    prep_kernel<<<512, 256>>>(wg, wn);
    gemm_kernel<<<N_TOKENS / 128, 256, 8 * STG_BYTE>>>(inp);
    gate_kernel<<<128, 256>>>(noise, out);
    refine_kernel<<<512, 256>>>(inp, wg, wn, noise, out);
    loss_kernel<<<1, 32>>>(out);
}

// round 4
// speedup vs baseline: 2.4495x; 2.4495x over previous
#include <cuda_runtime.h>
#include <cuda_bf16.h>
#include <cstdint>

// ---------------- problem constants ----------------
#define N_TOKENS 16384
#define D_MODEL  4096
#define N_EXP    64
#define N_OUT    128            // gate(64) || noise(64) logits
#define KC       32             // K chunk
#define ASTR     40             // smem row stride in bf16 (conflict-free for frag loads)
#define STG_ELEM (128 * ASTR)   // bf16 elements per stage per array = 5120
#define STG_BYTE (STG_ELEM * 2) // 10240
#define NC       (D_MODEL / KC) // 128 chunks
#define TAU      3e-4f          // near-tie refinement threshold (~10 sigma of GEMM error)

// ---------------- device scratch (no allocs allowed) ----------------
__device__ float          g_logits[(size_t)N_TOKENS * N_OUT];   // [t][0:64]=clean, [64:128]=raw_noise
__device__ __nv_bfloat16  g_bhi[(size_t)N_OUT * D_MODEL];       // W^T hi  [n][k]
__device__ __nv_bfloat16  g_blo[(size_t)N_OUT * D_MODEL];       // W^T lo  [n][k]
__device__ float          g_wt [(size_t)N_OUT * D_MODEL];       // W^T fp32 [n][k] (for exact refine)
__device__ float          g_imp[N_EXP];
__device__ float          g_load[N_EXP];
__device__ int            g_nflag;
__device__ int            g_flag[N_TOKENS];

// ---------------- cp.async helpers ----------------
#define CP_ASYNC16(dst, src)                                                        \
    asm volatile("cp.async.cg.shared.global [%0], [%1], 16;\n" ::"r"(dst), "l"(src))
#define CP_COMMIT()  asm volatile("cp.async.commit_group;\n" ::)
#define CP_WAIT1()   asm volatile("cp.async.wait_group 1;\n" ::)

// ---------------- prep: transpose + bf16 split + fp32 transpose, zero accumulators ----------------
__global__ void __launch_bounds__(256) prep_kernel(const float* __restrict__ wg,
                                                   const float* __restrict__ wn) {
    int gid = blockIdx.x * blockDim.x + threadIdx.x;
    if (gid < N_EXP) { g_imp[gid] = 0.f; g_load[gid] = 0.f; }
    if (gid == N_EXP) g_nflag = 0;
    int stride = gridDim.x * blockDim.x;
    const int total = N_OUT * D_MODEL;
    for (int i = gid; i < total; i += stride) {
        int n = i >> 12;          // /4096
        int k = i & 4095;
        float w = (n < N_EXP) ? wg[k * N_EXP + n] : wn[k * N_EXP + (n - N_EXP)];
        __nv_bfloat16 h = __float2bfloat16(w);
        g_bhi[i] = h;
        g_blo[i] = __float2bfloat16(w - __bfloat162float(h));
        g_wt[i]  = w;
    }
}

// ---------------- GEMM: logits = inp @ [w_gate | w_noise], fp32 via bf16 split ----------------
#define MMA_BF16(d, a, b0v, b1v)                                                    \
    asm volatile("mma.sync.aligned.m16n8k16.row.col.f32.bf16.bf16.f32 "             \
                 "{%0,%1,%2,%3}, {%4,%5,%6,%7}, {%8,%9}, {%0,%1,%2,%3};"            \
                 : "+f"(d[0]), "+f"(d[1]), "+f"(d[2]), "+f"(d[3])                   \
                 : "r"(a[0]), "r"(a[1]), "r"(a[2]), "r"(a[3]), "r"(b0v), "r"(b1v))

__global__ void __launch_bounds__(256) gemm_kernel(const float* __restrict__ inp) {
    extern __shared__ __nv_bfloat16 sm[];
    __nv_bfloat16* sAhi = sm;                    // [2][STG_ELEM]
    __nv_bfloat16* sAlo = sm + 2 * STG_ELEM;
    __nv_bfloat16* sBhi = sm + 4 * STG_ELEM;
    __nv_bfloat16* sBlo = sm + 6 * STG_ELEM;

    const int tid  = threadIdx.x;
    const int wid  = tid >> 5, lane = tid & 31;
    const int wm   = wid & 3;          // warp row tile (32 rows)
    const int wn   = wid >> 2;         // warp col tile (64 cols)
    const int g    = lane >> 2, tg = lane & 3;
    const int row0 = blockIdx.x * 128;

    float acc[2][8][4];
#pragma unroll
    for (int a = 0; a < 2; a++)
#pragma unroll
        for (int b = 0; b < 8; b++)
#pragma unroll
            for (int c = 0; c < 4; c++) acc[a][b][c] = 0.f;

    const int lr = tid >> 1;           // load row (A) / n (B)
    const int lc = (tid & 1) * 16;     // col base within chunk

    const float* aSrc = inp + (size_t)(row0 + lr) * D_MODEL + lc;
    const __nv_bfloat16* bhSrc = g_bhi + (size_t)lr * D_MODEL + lc;
    const __nv_bfloat16* blSrc = g_blo + (size_t)lr * D_MODEL + lc;
    const uint32_t sBhiAddr = (uint32_t)__cvta_generic_to_shared(sBhi) + (lr * ASTR + lc) * 2;
    const uint32_t sBloAddr = (uint32_t)__cvta_generic_to_shared(sBlo) + (lr * ASTR + lc) * 2;

    float4 aR[4];

#define CPB(c, s)                                                          \
    do {                                                                   \
        CP_ASYNC16(sBhiAddr + (s)*STG_BYTE,      bhSrc + (c)*KC);          \
        CP_ASYNC16(sBhiAddr + (s)*STG_BYTE + 16, bhSrc + (c)*KC + 8);      \
        CP_ASYNC16(sBloAddr + (s)*STG_BYTE,      blSrc + (c)*KC);          \
        CP_ASYNC16(sBloAddr + (s)*STG_BYTE + 16, blSrc + (c)*KC + 8);      \
    } while (0)

#define LDA(c)                                                             \
    do {                                                                   \
        _Pragma("unroll")                                                  \
        for (int u = 0; u < 4; u++)                                        \
            aR[u] = *reinterpret_cast<const float4*>(aSrc + (c)*KC + u*4); \
    } while (0)

#define CONVSTORE(s)                                                                   \
    do {                                                                               \
        int off0 = (s)*STG_ELEM + lr * ASTR + lc;                                      \
        _Pragma("unroll")                                                              \
        for (int u = 0; u < 4; u++) {                                                  \
            float4 v = aR[u];                                                          \
            __nv_bfloat16 h0 = __float2bfloat16(v.x);                                  \
            __nv_bfloat16 h1 = __float2bfloat16(v.y);                                  \
            __nv_bfloat16 h2 = __float2bfloat16(v.z);                                  \
            __nv_bfloat16 h3 = __float2bfloat16(v.w);                                  \
            __nv_bfloat16 l0 = __float2bfloat16(v.x - __bfloat162float(h0));           \
            __nv_bfloat16 l1 = __float2bfloat16(v.y - __bfloat162float(h1));           \
            __nv_bfloat16 l2 = __float2bfloat16(v.z - __bfloat162float(h2));           \
            __nv_bfloat16 l3 = __float2bfloat16(v.w - __bfloat162float(h3));           \
            int off = off0 + u * 4;                                                    \
            *reinterpret_cast<__nv_bfloat162*>(&sAhi[off])     = __halves2bfloat162(h0, h1); \
            *reinterpret_cast<__nv_bfloat162*>(&sAhi[off + 2]) = __halves2bfloat162(h2, h3); \
            *reinterpret_cast<__nv_bfloat162*>(&sAlo[off])     = __halves2bfloat162(l0, l1); \
            *reinterpret_cast<__nv_bfloat162*>(&sAlo[off + 2]) = __halves2bfloat162(l2, l3); \
        }                                                                              \
    } while (0)

    // ---- prologue ----
    LDA(0);
    CPB(0, 0); CP_COMMIT();        // group for chunk 0
    CONVSTORE(0);
    CPB(1, 1); CP_COMMIT();        // group for chunk 1
    LDA(1);
    CP_WAIT1();                    // chunk 0 B landed
    __syncthreads();

    for (int i = 0; i < NC; i++) {
        const int p = i & 1;
        const int ab = p * STG_ELEM;

#pragma unroll
        for (int ks = 0; ks < KC; ks += 16) {
            uint32_t ah[2][4], al[2][4];
#pragma unroll
            for (int mi = 0; mi < 2; mi++) {
                int r = wm * 32 + mi * 16 + g;
                int c = ks + tg * 2;
                ah[mi][0] = *reinterpret_cast<const uint32_t*>(&sAhi[ab + r * ASTR + c]);
                ah[mi][1] = *reinterpret_cast<const uint32_t*>(&sAhi[ab + (r + 8) * ASTR + c]);
                ah[mi][2] = *reinterpret_cast<const uint32_t*>(&sAhi[ab + r * ASTR + c + 8]);
                ah[mi][3] = *reinterpret_cast<const uint32_t*>(&sAhi[ab + (r + 8) * ASTR + c + 8]);
                al[mi][0] = *reinterpret_cast<const uint32_t*>(&sAlo[ab + r * ASTR + c]);
                al[mi][1] = *reinterpret_cast<const uint32_t*>(&sAlo[ab + (r + 8) * ASTR + c]);
                al[mi][2] = *reinterpret_cast<const uint32_t*>(&sAlo[ab + r * ASTR + c + 8]);
                al[mi][3] = *reinterpret_cast<const uint32_t*>(&sAlo[ab + (r + 8) * ASTR + c + 8]);
            }
#pragma unroll
            for (int ni = 0; ni < 8; ni++) {
                int nn = wn * 64 + ni * 8 + g;
                uint32_t bh0 = *reinterpret_cast<const uint32_t*>(&sBhi[ab + nn * ASTR + ks + tg * 2]);
                uint32_t bh1 = *reinterpret_cast<const uint32_t*>(&sBhi[ab + nn * ASTR + ks + tg * 2 + 8]);
                uint32_t bl0 = *reinterpret_cast<const uint32_t*>(&sBlo[ab + nn * ASTR + ks + tg * 2]);
                uint32_t bl1 = *reinterpret_cast<const uint32_t*>(&sBlo[ab + nn * ASTR + ks + tg * 2 + 8]);
#pragma unroll
                for (int mi = 0; mi < 2; mi++) {
                    MMA_BF16(acc[mi][ni], ah[mi], bh0, bh1);   // hi*hi
                    MMA_BF16(acc[mi][ni], al[mi], bh0, bh1);   // lo*hi
                    MMA_BF16(acc[mi][ni], ah[mi], bl0, bl1);   // hi*lo
                }
            }
        }
        __syncthreads();                         // all warps done reading stage p

        if (i + 1 < NC) {
            CONVSTORE(p ^ 1);                    // A for chunk i+1 (held in aR)
            if (i + 2 < NC) { CPB(i + 2, p); }   // B for chunk i+2 into freed stage p
            CP_COMMIT();                         // always commit (empty group ok)
            if (i + 2 < NC) { LDA(i + 2); }
            CP_WAIT1();                          // chunk i+1's B group complete
            __syncthreads();
        }
    }

    // epilogue -> g_logits [t][128]
#pragma unroll
    for (int mi = 0; mi < 2; mi++)
#pragma unroll
        for (int ni = 0; ni < 8; ni++) {
            int r = row0 + wm * 32 + mi * 16 + g;
            int c = wn * 64 + ni * 8 + tg * 2;
            *reinterpret_cast<float2*>(&g_logits[(size_t)r * N_OUT + c]) =
                make_float2(acc[mi][ni][0], acc[mi][ni][1]);
            *reinterpret_cast<float2*>(&g_logits[(size_t)(r + 8) * N_OUT + c]) =
                make_float2(acc[mi][ni][2], acc[mi][ni][3]);
        }
#undef CPB
#undef LDA
#undef CONVSTORE
}

// ---------------- gating helpers ----------------
__device__ __forceinline__ void warp_argmax(float& v, int& i) {
#pragma unroll
    for (int o = 16; o; o >>= 1) {
        float ov = __shfl_xor_sync(0xffffffffu, v, o);
        int   oi = __shfl_xor_sync(0xffffffffu, i, o);
        if (ov > v || (ov == v && oi < i)) { v = ov; i = oi; }
    }
}

// ---------------- gating pass 1: flag near-ties, process the rest ----------------
__global__ void __launch_bounds__(256) gate_kernel(const float* __restrict__ noise,
                                                   float* __restrict__ out) {
    __shared__ float s_imp[N_EXP];
    __shared__ float s_load[N_EXP];
    const int tid = threadIdx.x;
    if (tid < N_EXP) { s_imp[tid] = 0.f; s_load[tid] = 0.f; }
    __syncthreads();

    const int wid = tid >> 5, lane = tid & 31;
    const int e0 = 2 * lane, e1 = 2 * lane + 1;
    const int warpg = blockIdx.x * 8 + wid;   // 1024 warps total, 16 tokens each

    float li0 = 0.f, li1 = 0.f, ll0 = 0.f, ll1 = 0.f;

    for (int it = 0; it < 16; it++) {
        int t = warpg * 16 + it;
        const float* rowp = g_logits + (size_t)t * N_OUT;
        float2 cl = *reinterpret_cast<const float2*>(rowp + e0);
        float2 rn = *reinterpret_cast<const float2*>(rowp + 64 + e0);
        float2 nz = *reinterpret_cast<const float2*>(noise + (size_t)t * N_EXP + e0);

        float sp0 = fmaxf(rn.x, 0.f) + log1pf(expf(-fabsf(rn.x))) + 0.01f;
        float sp1 = fmaxf(rn.y, 0.f) + log1pf(expf(-fabsf(rn.y))) + 0.01f;
        float ny0 = cl.x + nz.x * sp0;
        float ny1 = cl.y + nz.y * sp1;

        // ---- top-3 with stable (lower index) tie-break ----
        float bv; int bi;
        if (ny0 >= ny1) { bv = ny0; bi = e0; } else { bv = ny1; bi = e1; }
        warp_argmax(bv, bi);
        float m1 = bv; int j1 = bi;

        float w0 = (e0 == j1) ? -3.4e38f : ny0;
        float w1 = (e1 == j1) ? -3.4e38f : ny1;
        if (w0 >= w1) { bv = w0; bi = e0; } else { bv = w1; bi = e1; }
        warp_argmax(bv, bi);
        float m2 = bv; int j2 = bi;

        w0 = (e0 == j2) ? -3.4e38f : w0;
        w1 = (e1 == j2) ? -3.4e38f : w1;
        if (w0 >= w1) { bv = w0; bi = e0; } else { bv = w1; bi = e1; }
        warp_argmax(bv, bi);
        float m3 = bv;

        // ---- near-tie? defer the whole token to the exact refine pass ----
        bool flagged = (m1 - m2 < TAU) || (m2 - m3 < TAU);
        if (flagged) {
            if (lane == 0) {
                int s = atomicAdd(&g_nflag, 1);
                g_flag[s] = t;
            }
            continue;
        }

        // ---- top-2 softmax ----
        float ee = expf(m2 - m1);
        float inv = 1.f / (1.f + ee);
        float gg0 = inv, gg1 = ee * inv;

        if (lane == 0) {
            out[2 * t]               = (float)j1;
            out[2 * t + 1]           = (float)j2;
            out[2 * N_TOKENS + 2 * t]     = gg0;
            out[2 * N_TOKENS + 2 * t + 1] = gg1;
        }

        // importance
        if (e0 == j1) li0 += gg0; else if (e0 == j2) li0 += gg1;
        if (e1 == j1) li1 += gg0; else if (e1 == j2) li1 += gg1;

        // load: threshold_if_in = 3rd largest (m3), else 2nd (m2)
        float thr0 = (ny0 > m3) ? m3 : m2;
        float thr1 = (ny1 > m3) ? m3 : m2;
        ll0 += normcdff((cl.x - thr0) / sp0);
        ll1 += normcdff((cl.y - thr1) / sp1);
    }

    atomicAdd(&s_imp[e0], li0);  atomicAdd(&s_imp[e1], li1);
    atomicAdd(&s_load[e0], ll0); atomicAdd(&s_load[e1], ll1);
    __syncthreads();
    if (tid < N_EXP) {
        atomicAdd(&g_imp[tid],  s_imp[tid]);
        atomicAdd(&g_load[tid], s_load[tid]);
    }
}

// ---------------- refine: fp64-exact logits for flagged tokens ----------------
// One warp per (token, column). Contiguous float4 streams from inp row and
// g_wt row -> high MLP, fully coalesced. Writes exact logits back into g_logits.
__global__ void __launch_bounds__(256) refine_kernel(const float* __restrict__ inp) {
    const int tid  = threadIdx.x;
    const int lane = tid & 31;
    const int W    = blockIdx.x * 8 + (tid >> 5);   // 0..4095
    const int slot = W >> 7;                        // 0..31 token slots per pass
    const int n    = W & 127;                       // output column
    const int nf   = g_nflag;

    for (int ii = slot; ii < nf; ii += 32) {
        const int t = g_flag[ii];
        const float4* ap = reinterpret_cast<const float4*>(inp + (size_t)t * D_MODEL);
        const float4* wp = reinterpret_cast<const float4*>(g_wt + (size_t)n * D_MODEL);
        double c0 = 0, c1 = 0, c2 = 0, c3 = 0;
#pragma unroll 4
        for (int j = 0; j < D_MODEL / 128; j++) {   // 32 iters, lane-strided float4
            float4 a = ap[j * 32 + lane];
            float4 b = wp[j * 32 + lane];
            c0 = fma((double)a.x, (double)b.x, c0);
            c1 = fma((double)a.y, (double)b.y, c1);
            c2 = fma((double)a.z, (double)b.z, c2);
            c3 = fma((double)a.w, (double)b.w, c3);
        }
        double s = (c0 + c1) + (c2 + c3);
#pragma unroll
        for (int o = 16; o; o >>= 1) s += __shfl_down_sync(0xffffffffu, s, o);
        if (lane == 0) g_logits[(size_t)t * N_OUT + n] = (float)s;
    }
}

// ---------------- refine2: gate math on exact logits (warp per flagged token) ----------------
__global__ void __launch_bounds__(256) refine2_kernel(const float* __restrict__ noise,
                                                      float* __restrict__ out) {
    const int tid  = threadIdx.x;
    const int lane = tid & 31;
    const int W    = blockIdx.x * 8 + (tid >> 5);
    const int nW   = gridDim.x * 8;
    const int nf   = g_nflag;
    const int e0 = 2 * lane, e1 = 2 * lane + 1;

    for (int ii = W; ii < nf; ii += nW) {
        const int t = g_flag[ii];
        const float* rowp = g_logits + (size_t)t * N_OUT;
        float cl0 = rowp[e0], cl1 = rowp[e1];
        float rn0 = rowp[64 + e0], rn1 = rowp[64 + e1];
        float nz0 = noise[(size_t)t * N_EXP + e0];
        float nz1 = noise[(size_t)t * N_EXP + e1];

        float sp0 = fmaxf(rn0, 0.f) + log1pf(expf(-fabsf(rn0))) + 0.01f;
        float sp1 = fmaxf(rn1, 0.f) + log1pf(expf(-fabsf(rn1))) + 0.01f;
        float ny0 = cl0 + nz0 * sp0;
        float ny1 = cl1 + nz1 * sp1;

        float bv; int bi;
        if (ny0 >= ny1) { bv = ny0; bi = e0; } else { bv = ny1; bi = e1; }
        warp_argmax(bv, bi);
        float m1 = bv; int j1 = bi;

        float w0 = (e0 == j1) ? -3.4e38f : ny0;
        float w1 = (e1 == j1) ? -3.4e38f : ny1;
        if (w0 >= w1) { bv = w0; bi = e0; } else { bv = w1; bi = e1; }
        warp_argmax(bv, bi);
        float m2 = bv; int j2 = bi;

        w0 = (e0 == j2) ? -3.4e38f : w0;
        w1 = (e1 == j2) ? -3.4e38f : w1;
        if (w0 >= w1) { bv = w0; bi = e0; } else { bv = w1; bi = e1; }
        warp_argmax(bv, bi);
        float m3 = bv;

        float ee  = expf(m2 - m1);
        float inv = 1.f / (1.f + ee);
        float gg0 = inv, gg1 = ee * inv;

        if (lane == 0) {
            out[2 * t]                    = (float)j1;
            out[2 * t + 1]                = (float)j2;
            out[2 * N_TOKENS + 2 * t]     = gg0;
            out[2 * N_TOKENS + 2 * t + 1] = gg1;
        }

        float li0 = 0.f, li1 = 0.f;
        if (e0 == j1) li0 = gg0; else if (e0 == j2) li0 = gg1;
        if (e1 == j1) li1 = gg0; else if (e1 == j2) li1 = gg1;

        float thr0 = (ny0 > m3) ? m3 : m2;
        float thr1 = (ny1 > m3) ? m3 : m2;
        float ll0 = normcdff((cl0 - thr0) / sp0);
        float ll1 = normcdff((cl1 - thr1) / sp1);

        if (li0 != 0.f) atomicAdd(&g_imp[e0], li0);
        if (li1 != 0.f) atomicAdd(&g_imp[e1], li1);
        atomicAdd(&g_load[e0], ll0);
        atomicAdd(&g_load[e1], ll1);
    }
}

// ---------------- loss: cv^2(importance) + cv^2(load) ----------------
__global__ void loss_kernel(float* __restrict__ out) {
    if (threadIdx.x == 0 && blockIdx.x == 0) {
        float loss = 0.f;
        for (int pass = 0; pass < 2; pass++) {
            const float* a = pass ? g_load : g_imp;
            float s = 0.f;
            for (int e = 0; e < N_EXP; e++) s += a[e];
            float mean = s * (1.f / N_EXP);
            float v = 0.f;
            for (int e = 0; e < N_EXP; e++) { float d = a[e] - mean; v += d * d; }
            v *= (1.f / (N_EXP - 1));
            loss += v / (mean * mean + 1e-10f);
        }
        out[2 * N_TOKENS * 2] = loss;   // index 65536
    }
}

// ---------------- launch ----------------
extern "C" void kernel_launch(void* const* d_in, const int* in_sizes, int n_in,
                              void* d_out, int out_size) {
    const float* inp   = (const float*)d_in[0];
    const float* wg    = (const float*)d_in[1];
    const float* wn    = (const float*)d_in[2];
    const float* noise = (const float*)d_in[3];
    float* out = (float*)d_out;

    static bool attr_done = false;
    if (!attr_done) {
        cudaFuncSetAttribute(gemm_kernel, cudaFuncAttributeMaxDynamicSharedMemorySize,
                             8 * STG_BYTE);
        attr_done = true;
    }

    prep_kernel<<<512, 256>>>(wg, wn);
    gemm_kernel<<<N_TOKENS / 128, 256, 8 * STG_BYTE>>>(inp);
    gate_kernel<<<128, 256>>>(noise, out);
    refine_kernel<<<512, 256>>>(inp);
    refine2_kernel<<<16, 256>>>(noise, out);
    loss_kernel<<<1, 32>>>(out);
}